// round 14
// baseline (speedup 1.0000x reference)
#include <cuda_runtime.h>
#include <cuda_bf16.h>
#include <math.h>

#define TN 200
#define BN 256
#define EN 300
#define HN 512
#define GN 1536            // 3*H
#define MN (TN*BN)         // 51200
#define KP 320             // padded K for input projection

typedef unsigned long long ull;
typedef unsigned int u32;

// ---------------- static device scratch ----------------
__device__ __align__(128) float g_xproj[(size_t)2 * TN * BN * GN];   // [dir][t*B+b][3H]
__device__ __align__(128) float g_out  [(size_t)2 * TN * BN * HN];   // [dir][t][b][H]
// h exchange in FRAGMENT-NATIVE layout: elem(b,k) = ((k>>4)*BN + b)*16 + (k&15)
__device__ __align__(128) __nv_bfloat16 g_hbh[2 * 2 * HN * BN];      // h bf16 hi
__device__ __align__(128) __nv_bfloat16 g_hbl[2 * 2 * HN * BN];      // h bf16 lo
__device__ __align__(128) __nv_bfloat16 g_ibh[(size_t)MN * KP];      // inp bf16 hi (padded)
__device__ __align__(128) __nv_bfloat16 g_ibl[(size_t)MN * KP];      // inp bf16 lo
__device__ __align__(128) __nv_bfloat16 g_wbh[2 * GN * KP];          // W_ih bf16 hi
__device__ __align__(128) __nv_bfloat16 g_wbl[2 * GN * KP];          // W_ih bf16 lo
__device__ u32   g_bar[8];
__device__ float g_v    [2 * HN];
__device__ int   g_inv  [BN];
__device__ float g_logits[BN * TN];

// ---------------- helpers ----------------
__device__ __forceinline__ float sigf(float x) { return 1.0f / (1.0f + __expf(-x)); }
__device__ __forceinline__ float tanhfast(float x) {
    float e = __expf(2.0f * x);
    return (e - 1.0f) / (e + 1.0f);
}
__device__ __forceinline__ u32 smem_u32(const void* p) {
    return (u32)__cvta_generic_to_shared(p);
}
__device__ __forceinline__ void cpa16(u32 s, const void* g) {
    asm volatile("cp.async.cg.shared.global [%0], [%1], 16;" :: "r"(s), "l"(g));
}
__device__ __forceinline__ void cpa_commit() { asm volatile("cp.async.commit_group;"); }
__device__ __forceinline__ void cpa_wait0()  { asm volatile("cp.async.wait_group 0;"); }

__device__ __forceinline__ void ldsm4(u32 addr, u32& r0, u32& r1, u32& r2, u32& r3) {
    asm volatile("ldmatrix.sync.aligned.m8n8.x4.shared.b16 {%0,%1,%2,%3}, [%4];"
                 : "=r"(r0), "=r"(r1), "=r"(r2), "=r"(r3) : "r"(addr));
}
__device__ __forceinline__ void mma_bf16(float* d, const u32* a, const u32* b) {
    asm volatile("mma.sync.aligned.m16n8k16.row.col.f32.bf16.bf16.f32 "
                 "{%0,%1,%2,%3}, {%4,%5,%6,%7}, {%8,%9}, {%0,%1,%2,%3};"
                 : "+f"(d[0]), "+f"(d[1]), "+f"(d[2]), "+f"(d[3])
                 : "r"(a[0]), "r"(a[1]), "r"(a[2]), "r"(a[3]), "r"(b[0]), "r"(b[1]));
}
__device__ __forceinline__ void split_bf16(float x, __nv_bfloat16& hi, __nv_bfloat16& lo) {
    hi = __float2bfloat16(x);
    lo = __float2bfloat16(x - __bfloat162float(hi));
}
__device__ __forceinline__ void bar_arrive(u32* p) {
    asm volatile("red.release.gpu.global.add.u32 [%0], %1;" :: "l"(p), "r"(1u) : "memory");
}
__device__ __forceinline__ u32 bar_peek(u32* p) {
    u32 v;
    asm volatile("ld.acquire.gpu.global.u32 %0, [%1];" : "=r"(v) : "l"(p) : "memory");
    return v;
}
__device__ __forceinline__ void fence_rel() {
    asm volatile("fence.acq_rel.gpu;" ::: "memory");
}
__device__ __forceinline__ u32 ldcg(const u32* p) {
    u32 v;
    asm volatile("ld.global.cg.b32 %0, [%1];" : "=r"(v) : "l"(p));
    return v;
}
__device__ __forceinline__ void stcs2(float* p, float x, float y) {
    asm volatile("st.global.cs.v2.f32 [%0], {%1, %2};" :: "l"(p), "f"(x), "f"(y) : "memory");
}
__device__ __forceinline__ float2 ldcs2(const float* p) {
    float2 v;
    asm volatile("ld.global.cs.v2.f32 {%0, %1}, [%2];" : "=f"(v.x), "=f"(v.y) : "l"(p));
    return v;
}

// ---------------- init ----------------
__global__ void init_kernel() {
    int i = blockIdx.x * blockDim.x + threadIdx.x;
    if (i < 2 * 2 * BN * HN) {
        g_hbh[i] = __float2bfloat16(0.0f);
        g_hbl[i] = __float2bfloat16(0.0f);
    }
    if (i < BN * TN) g_logits[i] = 0.0f;
    if (i < 8) g_bar[i] = 0u;
}

// ---------------- prep: v = W_comb @ W_attn, inverse perm ----------------
__global__ void prep_kernel(const float* __restrict__ Wattn,
                            const float* __restrict__ Wcomb,
                            const int*   __restrict__ sidx) {
    int tid = threadIdx.x;   // 1024
    float s = 0.0f;
    for (int m = 0; m < 2 * HN; m++)
        s += Wcomb[m] * Wattn[(size_t)m * (2 * HN) + tid];
    g_v[tid] = s;
    if (tid < BN) g_inv[sidx[tid]] = tid;
}

// ---------------- convert inp to bf16 hi/lo (padded K) ----------------
__global__ void convi_kernel(const float* __restrict__ inp) {
    size_t i = (size_t)blockIdx.x * blockDim.x + threadIdx.x;
    if (i < (size_t)MN * KP) {
        int m = (int)(i / KP), k = (int)(i % KP);
        float x = (k < EN) ? inp[(size_t)m * EN + k] : 0.0f;
        __nv_bfloat16 hi, lo;
        split_bf16(x, hi, lo);
        g_ibh[i] = hi; g_ibl[i] = lo;
    }
}

// ---------------- convert W_ih to bf16 hi/lo (padded K) ----------------
__global__ void convw_kernel(const float* __restrict__ Wf,
                             const float* __restrict__ Wb) {
    int i = blockIdx.x * blockDim.x + threadIdx.x;
    if (i < 2 * GN * KP) {
        int d = i / (GN * KP);
        int r = (i / KP) % GN;
        int k = i % KP;
        const float* W = d ? Wb : Wf;
        float x = (k < EN) ? W[(size_t)r * EN + k] : 0.0f;
        __nv_bfloat16 hi, lo;
        split_bf16(x, hi, lo);
        g_wbh[i] = hi; g_wbl[i] = lo;
    }
}

// ---------------- input projection: bf16-split tensor-core GEMM ----------------
#define PAARR (128*40*2)
#define PBARR (96*40*2)
#define PABUF (2*PAARR)
#define PBBUF (2*PBARR)
#define PSTAGE (PABUF+PBBUF)
#define PSMEM (2*PSTAGE)

__global__ __launch_bounds__(256) void proj_mma(const float* __restrict__ bf_,
                                                const float* __restrict__ bb_) {
    extern __shared__ __align__(16) char ps[];
    u32 smb = smem_u32(ps);
    int dir = blockIdx.z;
    int m0 = blockIdx.x * 128;
    int n0 = blockIdx.y * 96;
    const float* bias = dir ? bb_ : bf_;
    int tid = threadIdx.x, lane = tid & 31, w = tid >> 5;
    int wr = w & 3, c = w >> 2;
    int ql = lane & 3, rl = lane >> 2;

    const __nv_bfloat16* Wh = g_wbh + (size_t)dir * GN * KP;
    const __nv_bfloat16* Wl = g_wbl + (size_t)dir * GN * KP;

    u32 aDst[4]; const __nv_bfloat16* aSrc[4];
#pragma unroll
    for (int p = 0; p < 4; p++) {
        int idx = tid + 256 * p;
        int sel = idx >> 9, q = idx & 511, r = q >> 2, ch = q & 3;
        aDst[p] = smb + sel * PAARR + (u32)((r * 40 + ch * 8) * 2);
        aSrc[p] = (sel ? g_ibl : g_ibh) + (size_t)(m0 + r) * KP + ch * 8;
    }
    u32 bDst[3]; const __nv_bfloat16* bSrc[3];
#pragma unroll
    for (int p = 0; p < 3; p++) {
        int idx = tid + 256 * p;
        int sel = idx >= 384;
        int q = sel ? idx - 384 : idx;
        int r = q >> 2, ch = q & 3;
        bDst[p] = smb + PABUF + sel * PBARR + (u32)((r * 40 + ch * 8) * 2);
        bSrc[p] = (sel ? Wl : Wh) + (size_t)(n0 + r) * KP + ch * 8;
    }

    u32 aB[2][2];
#pragma unroll
    for (int mf = 0; mf < 2; mf++) {
        u32 off = (u32)(((wr * 32 + mf * 16 + (lane & 15)) * 40 + (lane >> 4) * 8) * 2);
        aB[mf][0] = smb + off; aB[mf][1] = smb + PAARR + off;
    }
    int rowB = c * 48 + (lane & 7) + ((lane >> 4) << 3);
    u32 bB[3][2];
#pragma unroll
    for (int p = 0; p < 3; p++) {
        u32 off = PABUF + (u32)(((rowB + p * 16) * 40 + ((lane >> 3) & 1) * 8) * 2);
        bB[p][0] = smb + off; bB[p][1] = smb + PBARR + off;
    }

    float d[2][6][4];
#pragma unroll
    for (int mf = 0; mf < 2; mf++)
#pragma unroll
        for (int n = 0; n < 6; n++)
#pragma unroll
            for (int q = 0; q < 4; q++) d[mf][n][q] = 0.0f;

#pragma unroll
    for (int p = 0; p < 4; p++) cpa16(aDst[p], aSrc[p]);
#pragma unroll
    for (int p = 0; p < 3; p++) cpa16(bDst[p], bSrc[p]);
    cpa_commit();

    for (int ck = 0; ck < 10; ck++) {
        int st = ck & 1;
        cpa_wait0();
        __syncthreads();
        if (ck + 1 < 10) {
            int ns = (ck + 1) & 1;
#pragma unroll
            for (int p = 0; p < 4; p++) cpa16(aDst[p] + ns * PSTAGE, aSrc[p] + (ck + 1) * 32);
#pragma unroll
            for (int p = 0; p < 3; p++) cpa16(bDst[p] + ns * PSTAGE, bSrc[p] + (ck + 1) * 32);
            cpa_commit();
        }
#pragma unroll
        for (int k16 = 0; k16 < 2; k16++) {
            u32 ko = st * PSTAGE + k16 * 32;
            u32 bhv[3][4], blv[3][4];
#pragma unroll
            for (int p = 0; p < 3; p++) {
                ldsm4(bB[p][0] + ko, bhv[p][0], bhv[p][1], bhv[p][2], bhv[p][3]);
                ldsm4(bB[p][1] + ko, blv[p][0], blv[p][1], blv[p][2], blv[p][3]);
            }
#pragma unroll
            for (int mf = 0; mf < 2; mf++) {
                u32 ah[4], al[4];
                ldsm4(aB[mf][0] + ko, ah[0], ah[1], ah[2], ah[3]);
                ldsm4(aB[mf][1] + ko, al[0], al[1], al[2], al[3]);
#pragma unroll
                for (int p = 0; p < 3; p++) {
                    mma_bf16(d[mf][2 * p],     ah, &bhv[p][0]);
                    mma_bf16(d[mf][2 * p],     ah, &blv[p][0]);
                    mma_bf16(d[mf][2 * p],     al, &bhv[p][0]);
                    mma_bf16(d[mf][2 * p + 1], ah, &bhv[p][2]);
                    mma_bf16(d[mf][2 * p + 1], ah, &blv[p][2]);
                    mma_bf16(d[mf][2 * p + 1], al, &bhv[p][2]);
                }
            }
        }
    }

#pragma unroll
    for (int nfr = 0; nfr < 6; nfr++) {
        int n = n0 + c * 48 + nfr * 8 + ql * 2;
        float2 b2 = *(const float2*)&bias[n];
#pragma unroll
        for (int mf = 0; mf < 2; mf++) {
            int m = m0 + wr * 32 + mf * 16 + rl;
            float* o0 = &g_xproj[((size_t)dir * MN + m) * GN + n];
            float* o1 = &g_xproj[((size_t)dir * MN + m + 8) * GN + n];
            *(float2*)o0 = make_float2(d[mf][nfr][0] + b2.x, d[mf][nfr][1] + b2.y);
            *(float2*)o1 = make_float2(d[mf][nfr][2] + b2.x, d[mf][nfr][3] + b2.y);
        }
    }
}

// ---------------- persistent GRU kernel: sync-free k-loop, deep register lookahead ----
// 128 blocks = 16 jt x 4 bt x 2 dir, 1 CTA/SM. Block: 32 j x 3 gates x 64 b, K=512.
// Weights resident in smem (ldsm, sync-free). A (h) read via ld.global.cg in
// fragment-native layout, 4 register buffers, lookahead 3 k32-chunks (~860cyc cover).
// Zero __syncthreads in the entire time loop; per-warp group barrier (R10-proven).
#define WST 520
#define WBYTES (96 * WST * 2)       // 99840
#define SMEM_TOTAL (2 * WBYTES)     // 199680

__global__ __launch_bounds__(256, 1) void persist_kernel(
    const float* __restrict__ Whf, const float* __restrict__ Whb,
    const float* __restrict__ bhf, const float* __restrict__ bhb,
    const int*   __restrict__ slen, const int* __restrict__ sidx)
{
    extern __shared__ __align__(16) char smem[];
    __nv_bfloat16* sWh = (__nv_bfloat16*)smem;
    __nv_bfloat16* sWl = sWh + 96 * WST;

    int jt = blockIdx.x, bt = blockIdx.y, dir = blockIdx.z;
    int j0 = jt * 32, b0 = bt * 64;
    int tid = threadIdx.x, lane = tid & 31, w = tid >> 5;
    int wr = w & 3;        // warp row: 16 b each
    int c  = w >> 2;       // warp col: 48 gate-cols each
    int ql = lane & 3, rl = lane >> 2;
    const float* W  = dir ? Whb : Whf;
    const float* bh = dir ? bhb : bhf;
    int grp = dir * 4 + bt;
    int Lg = slen[b0];

    // ---- resident weights: physical row p = (jj>>4)*48 + (((jj>>3)&1)*3+g)*8 + (jj&7)
    for (int i = tid; i < 96 * 128; i += 256) {
        int rw_ = i >> 7;
        int g = rw_ >> 5, jj = rw_ & 31;
        int k4 = (i & 127) * 4;
        float4 v = *(const float4*)&W[(size_t)(g * HN + j0 + jj) * HN + k4];
        int p = (jj >> 4) * 48 + (((jj >> 3) & 1) * 3 + g) * 8 + (jj & 7);
        const float* vs = (const float*)&v;
#pragma unroll
        for (int u = 0; u < 4; u++) {
            __nv_bfloat16 hi, lo;
            split_bf16(vs[u], hi, lo);
            sWh[p * WST + k4 + u] = hi;
            sWl[p * WST + k4 + u] = lo;
        }
    }
    __syncthreads();

    // ---- per-thread constants ----
    int jbase = j0 + c * 16 + ql * 2;
    float2 biasv[3][2];
#pragma unroll
    for (int g = 0; g < 3; g++)
#pragma unroll
        for (int jg = 0; jg < 2; jg++)
            biasv[g][jg] = *(const float2*)&bh[g * HN + jbase + jg * 8];
    float2 vv[2];
#pragma unroll
    for (int jg = 0; jg < 2; jg++)
        vv[jg] = *(const float2*)&g_v[dir * HN + jbase + jg * 8];
    int sl0 = slen[b0 + wr * 16 + rl];
    int sl1 = slen[b0 + wr * 16 + rl + 8];
    int sob0 = sidx[b0 + wr * 16 + rl];
    int sob1 = sidx[b0 + wr * 16 + rl + 8];

    float hold[2][2][2];
#pragma unroll
    for (int a = 0; a < 2; a++)
#pragma unroll
        for (int b = 0; b < 2; b++)
#pragma unroll
            for (int d2 = 0; d2 < 2; d2++) hold[a][b][d2] = 0.0f;

    // A fragment base (u32 index): elem(b,k) = ((k>>4)*BN + b)*16 + (k&15)
    u32 aBaseU = (u32)((b0 + wr * 16 + rl) * 8 + ql);

    // B ldsm bases (resident weights)
    int rowB = c * 48 + (lane & 7) + ((lane >> 4) << 3);
    u32 bBaseH[3], bBaseL[3];
#pragma unroll
    for (int p = 0; p < 3; p++) {
        u32 off = (u32)(((rowB + p * 16) * WST + ((lane >> 3) & 1) * 8) * 2);
        bBaseH[p] = smem_u32(sWh) + off;
        bBaseL[p] = smem_u32(sWl) + off;
    }

    // A load for one k32 chunk into buffer s (8 hi + 8 lo u32)
#define LDA32(s, ck) do {                                                  \
        u32 o0 = aBaseU + (u32)(2 * (ck)) * 2048;                          \
        u32 o1 = o0 + 2048;                                                \
        AH[s][0] = ldcg(p0h + o0);      AH[s][1] = ldcg(p0h + o0 + 64);    \
        AH[s][2] = ldcg(p0h + o0 + 4);  AH[s][3] = ldcg(p0h + o0 + 68);    \
        AH[s][4] = ldcg(p0h + o1);      AH[s][5] = ldcg(p0h + o1 + 64);    \
        AH[s][6] = ldcg(p0h + o1 + 4);  AH[s][7] = ldcg(p0h + o1 + 68);    \
        AL[s][0] = ldcg(p0l + o0);      AL[s][1] = ldcg(p0l + o0 + 64);    \
        AL[s][2] = ldcg(p0l + o0 + 4);  AL[s][3] = ldcg(p0l + o0 + 68);    \
        AL[s][4] = ldcg(p0l + o1);      AL[s][5] = ldcg(p0l + o1 + 64);    \
        AL[s][6] = ldcg(p0l + o1 + 4);  AL[s][7] = ldcg(p0l + o1 + 68);    \
    } while (0)

#define BCHUNK32(ck, s) do {                                               \
        _Pragma("unroll")                                                  \
        for (int k16 = 0; k16 < 2; k16++) {                                \
            const u32* ah = &AH[s][k16 * 4];                               \
            const u32* al = &AL[s][k16 * 4];                               \
            u32 kb = (u32)((2 * (ck) + k16) * 32);                         \
            _Pragma("unroll")                                              \
            for (int p = 0; p < 3; p++) {                                  \
                u32 bhv[4], blv[4];                                        \
                ldsm4(bBaseH[p] + kb, bhv[0], bhv[1], bhv[2], bhv[3]);     \
                ldsm4(bBaseL[p] + kb, blv[0], blv[1], blv[2], blv[3]);     \
                mma_bf16(d[2 * p],     ah, &bhv[0]);                       \
                mma_bf16(d[2 * p],     ah, &blv[0]);                       \
                mma_bf16(d[2 * p],     al, &bhv[0]);                       \
                mma_bf16(d[2 * p + 1], ah, &bhv[2]);                       \
                mma_bf16(d[2 * p + 1], ah, &blv[2]);                       \
                mma_bf16(d[2 * p + 1], al, &bhv[2]);                       \
            }                                                              \
        }                                                                  \
    } while (0)

    // ---- time loop ----
    for (int i = 0; i < Lg; i++) {
        int pp = i & 1;
        int tt = dir ? (Lg - 1 - i) : i;

        // xproj prefetch (overlaps barrier spin)
        float2 xpre[2][2][3];
        const float* xb = g_xproj + ((size_t)dir * MN + (size_t)tt * BN) * GN;
#pragma unroll
        for (int h2 = 0; h2 < 2; h2++) {
            int b = b0 + wr * 16 + rl + h2 * 8;
            const float* xr = xb + (size_t)b * GN;
#pragma unroll
            for (int jg = 0; jg < 2; jg++)
#pragma unroll
                for (int g = 0; g < 3; g++)
                    xpre[h2][jg][g] = ldcs2(&xr[g * HN + jbase + jg * 8]);
        }

        if (i) {
            if (lane == 0) {
                u32 target = 128u * (u32)i;
                while (bar_peek(&g_bar[grp]) < target) {}
            }
            __syncwarp();
        }

        const u32* p0h = (const u32*)(g_hbh + (size_t)(dir * 2 + pp) * HN * BN);
        const u32* p0l = (const u32*)(g_hbl + (size_t)(dir * 2 + pp) * HN * BN);
        __nv_bfloat16* hbd = g_hbh + (size_t)(dir * 2 + (pp ^ 1)) * HN * BN;
        __nv_bfloat16* hld = g_hbl + (size_t)(dir * 2 + (pp ^ 1)) * HN * BN;

        float d[6][4];
#pragma unroll
        for (int n = 0; n < 6; n++)
#pragma unroll
            for (int q = 0; q < 4; q++) d[n][q] = 0.0f;

        // sync-free k-loop: 4 register buffers, lookahead 3 chunks
        u32 AH[4][8], AL[4][8];
        LDA32(0, 0);
        LDA32(1, 1);
        LDA32(2, 2);
#pragma unroll
        for (int ck = 0; ck < 16; ck++) {
            if (ck + 3 < 16) LDA32((ck + 3) & 3, ck + 3);
            BCHUNK32(ck, ck & 3);
        }

        // ---- epilogue phase 1: compute h, store ONLY h (fragment layout) ----
        float oo[2][2][2];
#pragma unroll
        for (int h2 = 0; h2 < 2; h2++) {
            int b = b0 + wr * 16 + rl + h2 * 8;
            bool m = tt < (h2 ? sl1 : sl0);
#pragma unroll
            for (int jg = 0; jg < 2; jg++) {
                int j = jbase + jg * 8;
                float ho[2];
#pragma unroll
                for (int cc = 0; cc < 2; cc++) {
                    int q = h2 * 2 + cc;
                    const float* xR = (const float*)&xpre[h2][jg][0];
                    const float* xZ = (const float*)&xpre[h2][jg][1];
                    const float* xN = (const float*)&xpre[h2][jg][2];
                    const float* bR = (const float*)&biasv[0][jg];
                    const float* bZ = (const float*)&biasv[1][jg];
                    const float* bNp = (const float*)&biasv[2][jg];
                    float r = sigf(xR[cc] + d[jg * 3 + 0][q] + bR[cc]);
                    float z = sigf(xZ[cc] + d[jg * 3 + 1][q] + bZ[cc]);
                    float n = tanhfast(xN[cc] + r * (d[jg * 3 + 2][q] + bNp[cc]));
                    float hprev = hold[h2][jg][cc];
                    float hv = (1.0f - z) * n + z * hprev;
                    float hout = m ? hv : hprev;
                    hold[h2][jg][cc] = hout;
                    ho[cc] = hout;
                    oo[h2][jg][cc] = m ? hv : 0.0f;
                }
                __nv_bfloat16 hi0, lo0, hi1, lo1;
                split_bf16(ho[0], hi0, lo0);
                split_bf16(ho[1], hi1, lo1);
                __nv_bfloat162 hp; hp.x = hi0; hp.y = hi1;
                __nv_bfloat162 lq; lq.x = lo0; lq.y = lo1;
                // fragment-native: elem = ((j>>4)*BN + b)*16 + (j&15)
                size_t eidx = ((size_t)(j >> 4) * BN + b) * 16 + (j & 15);
                *(__nv_bfloat162*)&hbd[eidx] = hp;
                *(__nv_bfloat162*)&hld[eidx] = lq;
            }
        }

        // ---- per-warp arrive: release-fence + release-atomic ----
        if (i + 1 < Lg) {
            fence_rel();
            __syncwarp();
            if (lane == 0) bar_arrive(&g_bar[grp]);
        }

        // ---- epilogue phase 2 (off critical path): g_out + logits ----
        float lp[2] = {0.0f, 0.0f};
#pragma unroll
        for (int h2 = 0; h2 < 2; h2++) {
            int b = b0 + wr * 16 + rl + h2 * 8;
#pragma unroll
            for (int jg = 0; jg < 2; jg++) {
                int j = jbase + jg * 8;
                stcs2(&g_out[(((size_t)dir * TN + tt) * BN + b) * HN + j],
                      oo[h2][jg][0], oo[h2][jg][1]);
                lp[h2] += oo[h2][jg][0] * ((const float*)&vv[jg])[0]
                        + oo[h2][jg][1] * ((const float*)&vv[jg])[1];
            }
        }
#pragma unroll
        for (int h2 = 0; h2 < 2; h2++) {
            lp[h2] += __shfl_xor_sync(0xffffffff, lp[h2], 1);
            lp[h2] += __shfl_xor_sync(0xffffffff, lp[h2], 2);
            if (ql == 0 && lp[h2] != 0.0f)
                atomicAdd(&g_logits[(size_t)(h2 ? sob1 : sob0) * TN + tt], lp[h2]);
        }
    }
#undef LDA32
#undef BCHUNK32
}

// ---------------- fused softmax + weighted sum ----------------
__global__ __launch_bounds__(256) void attn_kernel(const int* __restrict__ seqlen,
                                                   float* __restrict__ out) {
    __shared__ float sa[256];
    __shared__ float red[256];
    int ob = blockIdx.x;
    int tid = threadIdx.x;
    int len = seqlen[ob];
    bool valid = (tid < TN) && (tid < len);
    float l = valid ? g_logits[(size_t)ob * TN + tid] : -1e30f;

    red[tid] = l;
    __syncthreads();
    for (int s = 128; s > 0; s >>= 1) {
        if (tid < s) red[tid] = fmaxf(red[tid], red[tid + s]);
        __syncthreads();
    }
    float mx = red[0];
    __syncthreads();
    float e = valid ? expf(l - mx) : 0.0f;
    red[tid] = e;
    __syncthreads();
    for (int s = 128; s > 0; s >>= 1) {
        if (tid < s) red[tid] += red[tid + s];
        __syncthreads();
    }
    sa[tid] = e / red[0];
    __syncthreads();

    int jb = g_inv[ob];
#pragma unroll
    for (int q = 0; q < 4; q++) {
        int h = q * 256 + tid;
        int d = (h >= HN);
        int hc = d ? h - HN : h;
        const float* base = g_out + ((size_t)d * TN * BN + jb) * HN + hc;
        float acc = 0.0f;
        for (int t = 0; t < len; t++)
            acc += sa[t] * base[(size_t)t * BN * HN];
        out[(size_t)ob * (2 * HN) + h] = acc;
    }
}

// ---------------- launch ----------------
extern "C" void kernel_launch(void* const* d_in, const int* in_sizes, int n_in,
                              void* d_out, int out_size) {
    const float* inp    = (const float*)d_in[0];
    const float* Wih_f  = (const float*)d_in[1];
    const float* Whh_f  = (const float*)d_in[2];
    const float* bih_f  = (const float*)d_in[3];
    const float* bhh_f  = (const float*)d_in[4];
    const float* Wih_b  = (const float*)d_in[5];
    const float* Whh_b  = (const float*)d_in[6];
    const float* bih_b  = (const float*)d_in[7];
    const float* bhh_b  = (const float*)d_in[8];
    const float* Wattn  = (const float*)d_in[9];
    const float* Wcomb  = (const float*)d_in[11];
    const int*   slen_s = (const int*)d_in[12];
    const int*   sidx   = (const int*)d_in[13];
    const int*   seqlen = (const int*)d_in[14];
    float* out = (float*)d_out;

    cudaFuncSetAttribute(persist_kernel,
                         cudaFuncAttributeMaxDynamicSharedMemorySize, SMEM_TOTAL);
    cudaFuncSetAttribute(proj_mma,
                         cudaFuncAttributeMaxDynamicSharedMemorySize, PSMEM);

    init_kernel<<<(2 * 2 * BN * HN + 255) / 256, 256>>>();
    prep_kernel<<<1, 1024>>>(Wattn, Wcomb, sidx);
    convi_kernel<<<(int)(((size_t)MN * KP + 255) / 256), 256>>>(inp);
    convw_kernel<<<(2 * GN * KP + 255) / 256, 256>>>(Wih_f, Wih_b);
    proj_mma<<<dim3(MN / 128, GN / 96, 2), 256, PSMEM>>>(bih_f, bih_b);
    persist_kernel<<<dim3(16, 4, 2), 256, SMEM_TOTAL>>>(Whh_f, Whh_b, bhh_f, bhh_b,
                                                        slen_s, sidx);
    attn_kernel<<<BN, 256>>>(seqlen, out);
}

// round 15
// speedup vs baseline: 1.5637x; 1.5637x over previous
#include <cuda_runtime.h>
#include <cuda_bf16.h>
#include <math.h>

#define TN 200
#define BN 256
#define EN 300
#define HN 512
#define GN 1536            // 3*H
#define MN (TN*BN)         // 51200
#define KP 320             // padded K for input projection

typedef unsigned long long ull;
typedef unsigned int u32;

// ---------------- static device scratch ----------------
__device__ __align__(128) float g_xproj[(size_t)2 * TN * BN * GN];   // [dir][t*B+b][3H]
__device__ __align__(128) float g_out  [(size_t)2 * TN * BN * HN];   // [dir][t][b][H]
__device__ __align__(128) __nv_bfloat16 g_hbh[2 * 2 * BN * HN];      // h bf16 hi [dir][pp][b][k]
__device__ __align__(128) __nv_bfloat16 g_hbl[2 * 2 * BN * HN];      // h bf16 lo
__device__ __align__(128) __nv_bfloat16 g_ibh[(size_t)MN * KP];      // inp bf16 hi (padded)
__device__ __align__(128) __nv_bfloat16 g_ibl[(size_t)MN * KP];      // inp bf16 lo
__device__ __align__(128) __nv_bfloat16 g_wbh[2 * GN * KP];          // W_ih bf16 hi
__device__ __align__(128) __nv_bfloat16 g_wbl[2 * GN * KP];          // W_ih bf16 lo
__device__ u32   g_bar[8];
__device__ float g_v    [2 * HN];
__device__ int   g_inv  [BN];
__device__ float g_logits[BN * TN];

// ---------------- helpers ----------------
__device__ __forceinline__ float sigf(float x) { return 1.0f / (1.0f + __expf(-x)); }
__device__ __forceinline__ float tanhfast(float x) {
    float e = __expf(2.0f * x);
    return (e - 1.0f) / (e + 1.0f);
}
__device__ __forceinline__ u32 smem_u32(const void* p) {
    return (u32)__cvta_generic_to_shared(p);
}
__device__ __forceinline__ void cpa16(u32 s, const void* g) {
    asm volatile("cp.async.cg.shared.global [%0], [%1], 16;" :: "r"(s), "l"(g));
}
__device__ __forceinline__ void cpa_commit() { asm volatile("cp.async.commit_group;"); }
__device__ __forceinline__ void cpa_wait0()  { asm volatile("cp.async.wait_group 0;"); }
__device__ __forceinline__ void cpa_wait1()  { asm volatile("cp.async.wait_group 1;"); }

__device__ __forceinline__ void ldsm4(u32 addr, u32& r0, u32& r1, u32& r2, u32& r3) {
    asm volatile("ldmatrix.sync.aligned.m8n8.x4.shared.b16 {%0,%1,%2,%3}, [%4];"
                 : "=r"(r0), "=r"(r1), "=r"(r2), "=r"(r3) : "r"(addr));
}
__device__ __forceinline__ void mma_bf16(float* d, const u32* a, const u32* b) {
    asm volatile("mma.sync.aligned.m16n8k16.row.col.f32.bf16.bf16.f32 "
                 "{%0,%1,%2,%3}, {%4,%5,%6,%7}, {%8,%9}, {%0,%1,%2,%3};"
                 : "+f"(d[0]), "+f"(d[1]), "+f"(d[2]), "+f"(d[3])
                 : "r"(a[0]), "r"(a[1]), "r"(a[2]), "r"(a[3]), "r"(b[0]), "r"(b[1]));
}
__device__ __forceinline__ void split_bf16(float x, __nv_bfloat16& hi, __nv_bfloat16& lo) {
    hi = __float2bfloat16(x);
    lo = __float2bfloat16(x - __bfloat162float(hi));
}
__device__ __forceinline__ void bar_arrive(u32* p) {
    asm volatile("red.release.gpu.global.add.u32 [%0], %1;" :: "l"(p), "r"(1u) : "memory");
}
__device__ __forceinline__ u32 bar_peek(u32* p) {
    u32 v;
    asm volatile("ld.acquire.gpu.global.u32 %0, [%1];" : "=r"(v) : "l"(p) : "memory");
    return v;
}

// ---------------- init ----------------
__global__ void init_kernel() {
    int i = blockIdx.x * blockDim.x + threadIdx.x;
    if (i < 2 * 2 * BN * HN) {
        g_hbh[i] = __float2bfloat16(0.0f);
        g_hbl[i] = __float2bfloat16(0.0f);
    }
    if (i < BN * TN) g_logits[i] = 0.0f;
    if (i < 8) g_bar[i] = 0u;
}

// ---------------- prep: v = W_comb @ W_attn, inverse perm ----------------
__global__ void prep_kernel(const float* __restrict__ Wattn,
                            const float* __restrict__ Wcomb,
                            const int*   __restrict__ sidx) {
    int tid = threadIdx.x;   // 1024
    float s = 0.0f;
    for (int m = 0; m < 2 * HN; m++)
        s += Wcomb[m] * Wattn[(size_t)m * (2 * HN) + tid];
    g_v[tid] = s;
    if (tid < BN) g_inv[sidx[tid]] = tid;
}

// ---------------- convert inp to bf16 hi/lo (padded K) ----------------
__global__ void convi_kernel(const float* __restrict__ inp) {
    size_t i = (size_t)blockIdx.x * blockDim.x + threadIdx.x;
    if (i < (size_t)MN * KP) {
        int m = (int)(i / KP), k = (int)(i % KP);
        float x = (k < EN) ? inp[(size_t)m * EN + k] : 0.0f;
        __nv_bfloat16 hi, lo;
        split_bf16(x, hi, lo);
        g_ibh[i] = hi; g_ibl[i] = lo;
    }
}

// ---------------- convert W_ih to bf16 hi/lo (padded K) ----------------
__global__ void convw_kernel(const float* __restrict__ Wf,
                             const float* __restrict__ Wb) {
    int i = blockIdx.x * blockDim.x + threadIdx.x;
    if (i < 2 * GN * KP) {
        int d = i / (GN * KP);
        int r = (i / KP) % GN;
        int k = i % KP;
        const float* W = d ? Wb : Wf;
        float x = (k < EN) ? W[(size_t)r * EN + k] : 0.0f;
        __nv_bfloat16 hi, lo;
        split_bf16(x, hi, lo);
        g_wbh[i] = hi; g_wbl[i] = lo;
    }
}

// ---------------- input projection: bf16-split tensor-core GEMM ----------------
#define PAARR (128*40*2)
#define PBARR (96*40*2)
#define PABUF (2*PAARR)
#define PBBUF (2*PBARR)
#define PSTAGE (PABUF+PBBUF)
#define PSMEM (2*PSTAGE)

__global__ __launch_bounds__(256) void proj_mma(const float* __restrict__ bf_,
                                                const float* __restrict__ bb_) {
    extern __shared__ __align__(16) char ps[];
    u32 smb = smem_u32(ps);
    int dir = blockIdx.z;
    int m0 = blockIdx.x * 128;
    int n0 = blockIdx.y * 96;
    const float* bias = dir ? bb_ : bf_;
    int tid = threadIdx.x, lane = tid & 31, w = tid >> 5;
    int wr = w & 3, c = w >> 2;
    int ql = lane & 3, rl = lane >> 2;

    const __nv_bfloat16* Wh = g_wbh + (size_t)dir * GN * KP;
    const __nv_bfloat16* Wl = g_wbl + (size_t)dir * GN * KP;

    u32 aDst[4]; const __nv_bfloat16* aSrc[4];
#pragma unroll
    for (int p = 0; p < 4; p++) {
        int idx = tid + 256 * p;
        int sel = idx >> 9, q = idx & 511, r = q >> 2, ch = q & 3;
        aDst[p] = smb + sel * PAARR + (u32)((r * 40 + ch * 8) * 2);
        aSrc[p] = (sel ? g_ibl : g_ibh) + (size_t)(m0 + r) * KP + ch * 8;
    }
    u32 bDst[3]; const __nv_bfloat16* bSrc[3];
#pragma unroll
    for (int p = 0; p < 3; p++) {
        int idx = tid + 256 * p;
        int sel = idx >= 384;
        int q = sel ? idx - 384 : idx;
        int r = q >> 2, ch = q & 3;
        bDst[p] = smb + PABUF + sel * PBARR + (u32)((r * 40 + ch * 8) * 2);
        bSrc[p] = (sel ? Wl : Wh) + (size_t)(n0 + r) * KP + ch * 8;
    }

    u32 aB[2][2];
#pragma unroll
    for (int mf = 0; mf < 2; mf++) {
        u32 off = (u32)(((wr * 32 + mf * 16 + (lane & 15)) * 40 + (lane >> 4) * 8) * 2);
        aB[mf][0] = smb + off; aB[mf][1] = smb + PAARR + off;
    }
    int rowB = c * 48 + (lane & 7) + ((lane >> 4) << 3);
    u32 bB[3][2];
#pragma unroll
    for (int p = 0; p < 3; p++) {
        u32 off = PABUF + (u32)(((rowB + p * 16) * 40 + ((lane >> 3) & 1) * 8) * 2);
        bB[p][0] = smb + off; bB[p][1] = smb + PBARR + off;
    }

    float d[2][6][4];
#pragma unroll
    for (int mf = 0; mf < 2; mf++)
#pragma unroll
        for (int n = 0; n < 6; n++)
#pragma unroll
            for (int q = 0; q < 4; q++) d[mf][n][q] = 0.0f;

#pragma unroll
    for (int p = 0; p < 4; p++) cpa16(aDst[p], aSrc[p]);
#pragma unroll
    for (int p = 0; p < 3; p++) cpa16(bDst[p], bSrc[p]);
    cpa_commit();

    for (int ck = 0; ck < 10; ck++) {
        int st = ck & 1;
        cpa_wait0();
        __syncthreads();
        if (ck + 1 < 10) {
            int ns = (ck + 1) & 1;
#pragma unroll
            for (int p = 0; p < 4; p++) cpa16(aDst[p] + ns * PSTAGE, aSrc[p] + (ck + 1) * 32);
#pragma unroll
            for (int p = 0; p < 3; p++) cpa16(bDst[p] + ns * PSTAGE, bSrc[p] + (ck + 1) * 32);
            cpa_commit();
        }
#pragma unroll
        for (int k16 = 0; k16 < 2; k16++) {
            u32 ko = st * PSTAGE + k16 * 32;
            u32 bhv[3][4], blv[3][4];
#pragma unroll
            for (int p = 0; p < 3; p++) {
                ldsm4(bB[p][0] + ko, bhv[p][0], bhv[p][1], bhv[p][2], bhv[p][3]);
                ldsm4(bB[p][1] + ko, blv[p][0], blv[p][1], blv[p][2], blv[p][3]);
            }
#pragma unroll
            for (int mf = 0; mf < 2; mf++) {
                u32 ah[4], al[4];
                ldsm4(aB[mf][0] + ko, ah[0], ah[1], ah[2], ah[3]);
                ldsm4(aB[mf][1] + ko, al[0], al[1], al[2], al[3]);
#pragma unroll
                for (int p = 0; p < 3; p++) {
                    mma_bf16(d[mf][2 * p],     ah, &bhv[p][0]);
                    mma_bf16(d[mf][2 * p],     ah, &blv[p][0]);
                    mma_bf16(d[mf][2 * p],     al, &bhv[p][0]);
                    mma_bf16(d[mf][2 * p + 1], ah, &bhv[p][2]);
                    mma_bf16(d[mf][2 * p + 1], ah, &blv[p][2]);
                    mma_bf16(d[mf][2 * p + 1], al, &bhv[p][2]);
                }
            }
        }
    }

#pragma unroll
    for (int nfr = 0; nfr < 6; nfr++) {
        int n = n0 + c * 48 + nfr * 8 + ql * 2;
        float2 b2 = *(const float2*)&bias[n];
#pragma unroll
        for (int mf = 0; mf < 2; mf++) {
            int m = m0 + wr * 32 + mf * 16 + rl;
            float* o0 = &g_xproj[((size_t)dir * MN + m) * GN + n];
            float* o1 = &g_xproj[((size_t)dir * MN + m + 8) * GN + n];
            *(float2*)o0 = make_float2(d[mf][nfr][0] + b2.x, d[mf][nfr][1] + b2.y);
            *(float2*)o1 = make_float2(d[mf][nfr][2] + b2.x, d[mf][nfr][3] + b2.y);
        }
    }
}

// ---------------- persistent GRU kernel (R6 structure; direct logits atomics) ----------
#define WST 520
#define AST 40
#define WBYTES (96 * WST * 2)       // 99840
#define AARR   (64 * AST * 2)       // 5120
#define ABUF   (2 * AARR)           // 10240 per stage
#define SMEM_TOTAL (2 * WBYTES + 3 * ABUF)   // 230400

__global__ __launch_bounds__(256, 1) void persist_kernel(
    const float* __restrict__ Whf, const float* __restrict__ Whb,
    const float* __restrict__ bhf, const float* __restrict__ bhb,
    const int*   __restrict__ slen, const int* __restrict__ sidx)
{
    extern __shared__ __align__(16) char smem[];
    __nv_bfloat16* sWh = (__nv_bfloat16*)smem;
    __nv_bfloat16* sWl = sWh + 96 * WST;
    char* sA = smem + 2 * WBYTES;

    int jt = blockIdx.x, bt = blockIdx.y, dir = blockIdx.z;
    int j0 = jt * 32, b0 = bt * 64;
    int tid = threadIdx.x, lane = tid & 31, w = tid >> 5;
    int wr = w & 3;
    int c  = w >> 2;
    int ql = lane & 3, rl = lane >> 2;
    const float* W  = dir ? Whb : Whf;
    const float* bh = dir ? bhb : bhf;
    int grp = dir * 4 + bt;
    int Lg = slen[b0];

    // ---- resident weights ----
    for (int i = tid; i < 96 * 128; i += 256) {
        int rw_ = i >> 7;
        int g = rw_ >> 5, jj = rw_ & 31;
        int k4 = (i & 127) * 4;
        float4 v = *(const float4*)&W[(size_t)(g * HN + j0 + jj) * HN + k4];
        int p = (jj >> 4) * 48 + (((jj >> 3) & 1) * 3 + g) * 8 + (jj & 7);
        const float* vs = (const float*)&v;
#pragma unroll
        for (int u = 0; u < 4; u++) {
            __nv_bfloat16 hi, lo;
            split_bf16(vs[u], hi, lo);
            sWh[p * WST + k4 + u] = hi;
            sWl[p * WST + k4 + u] = lo;
        }
    }
    __syncthreads();

    // ---- per-thread constants ----
    int jbase = j0 + c * 16 + ql * 2;
    float2 biasv[3][2];
#pragma unroll
    for (int g = 0; g < 3; g++)
#pragma unroll
        for (int jg = 0; jg < 2; jg++)
            biasv[g][jg] = *(const float2*)&bh[g * HN + jbase + jg * 8];
    float2 vv[2];
#pragma unroll
    for (int jg = 0; jg < 2; jg++)
        vv[jg] = *(const float2*)&g_v[dir * HN + jbase + jg * 8];
    int sl0 = slen[b0 + wr * 16 + rl];
    int sl1 = slen[b0 + wr * 16 + rl + 8];
    int sob0 = sidx[b0 + wr * 16 + rl];
    int sob1 = sidx[b0 + wr * 16 + rl + 8];

    float hold[2][2][2];
#pragma unroll
    for (int a = 0; a < 2; a++)
#pragma unroll
        for (int b = 0; b < 2; b++)
#pragma unroll
            for (int d2 = 0; d2 < 2; d2++) hold[a][b][d2] = 0.0f;

    int arrSel[2];
    size_t aOffG[2];
    u32 aOffS[2];
#pragma unroll
    for (int p = 0; p < 2; p++) {
        int idx = tid + 256 * p;
        arrSel[p] = idx >> 8;
        int r = (idx & 255) >> 2;
        int ch = idx & 3;
        aOffG[p] = (size_t)(b0 + r) * HN + ch * 8;
        aOffS[p] = smem_u32(sA) + (u32)(((arrSel[p] * 64 + r) * AST + ch * 8) * 2);
    }

    u32 aBaseH = smem_u32(sA) + (u32)(((wr * 16 + (lane & 15)) * AST + (lane >> 4) * 8) * 2);
    u32 aBaseL = aBaseH + AARR;
    int rowB = c * 48 + (lane & 7) + ((lane >> 4) << 3);
    u32 bBaseH[3], bBaseL[3];
#pragma unroll
    for (int p = 0; p < 3; p++) {
        u32 off = (u32)(((rowB + p * 16) * WST + ((lane >> 3) & 1) * 8) * 2);
        bBaseH[p] = smem_u32(sWh) + off;
        bBaseL[p] = smem_u32(sWl) + off;
    }

    // ---- time loop ----
    for (int i = 0; i < Lg; i++) {
        int pp = i & 1;
        int tt = dir ? (Lg - 1 - i) : i;

        // xproj prefetch (overlaps barrier spin)
        float2 xpre[2][2][3];
        const float* xb = g_xproj + ((size_t)dir * MN + (size_t)tt * BN) * GN;
#pragma unroll
        for (int h2 = 0; h2 < 2; h2++) {
            int b = b0 + wr * 16 + rl + h2 * 8;
            const float* xr = xb + (size_t)b * GN;
#pragma unroll
            for (int jg = 0; jg < 2; jg++)
#pragma unroll
                for (int g = 0; g < 3; g++)
                    xpre[h2][jg][g] = *(const float2*)&xr[g * HN + jbase + jg * 8];
        }

        if (i) {
            if (tid == 0) {
                u32 target = 16u * (u32)i;
                while (bar_peek(&g_bar[grp]) < target) {}
            }
            __syncthreads();
        }

        const __nv_bfloat16* hbp = g_hbh + (size_t)(dir * 2 + pp) * BN * HN;
        const __nv_bfloat16* hlp = g_hbl + (size_t)(dir * 2 + pp) * BN * HN;
        __nv_bfloat16* hbd = g_hbh + (size_t)(dir * 2 + (pp ^ 1)) * BN * HN;
        __nv_bfloat16* hld = g_hbl + (size_t)(dir * 2 + (pp ^ 1)) * BN * HN;
        const __nv_bfloat16* aSrc0 = (arrSel[0] ? hlp : hbp) + aOffG[0];
        const __nv_bfloat16* aSrc1 = (arrSel[1] ? hlp : hbp) + aOffG[1];

        float d[6][4];
#pragma unroll
        for (int n = 0; n < 6; n++)
#pragma unroll
            for (int q = 0; q < 4; q++) d[n][q] = 0.0f;

        cpa16(aOffS[0], aSrc0);
        cpa16(aOffS[1], aSrc1);
        cpa_commit();
        cpa16(aOffS[0] + ABUF, aSrc0 + 32);
        cpa16(aOffS[1] + ABUF, aSrc1 + 32);
        cpa_commit();

        for (int ck = 0; ck < 16; ck++) {
            if (ck < 15) cpa_wait1(); else cpa_wait0();
            __syncthreads();
            if (ck + 2 < 16) {
                int ns = (ck + 2) % 3;
                cpa16(aOffS[0] + ns * ABUF, aSrc0 + (ck + 2) * 32);
                cpa16(aOffS[1] + ns * ABUF, aSrc1 + (ck + 2) * 32);
                cpa_commit();
            }
            int st = ck % 3;
#pragma unroll
            for (int k16 = 0; k16 < 2; k16++) {
                int kk = ck * 2 + k16;
                u32 abo = st * ABUF + k16 * 32;
                u32 ah[4], al[4];
                ldsm4(aBaseH + abo, ah[0], ah[1], ah[2], ah[3]);
                ldsm4(aBaseL + abo, al[0], al[1], al[2], al[3]);
                u32 kb = kk * 32;
#pragma unroll
                for (int p = 0; p < 3; p++) {
                    u32 bhv[4], blv[4];
                    ldsm4(bBaseH[p] + kb, bhv[0], bhv[1], bhv[2], bhv[3]);
                    ldsm4(bBaseL[p] + kb, blv[0], blv[1], blv[2], blv[3]);
                    mma_bf16(d[2 * p],     ah, &bhv[0]);
                    mma_bf16(d[2 * p],     ah, &blv[0]);
                    mma_bf16(d[2 * p],     al, &bhv[0]);
                    mma_bf16(d[2 * p + 1], ah, &bhv[2]);
                    mma_bf16(d[2 * p + 1], ah, &blv[2]);
                    mma_bf16(d[2 * p + 1], al, &bhv[2]);
                }
            }
        }

        // ---- epilogue phase 1: compute h, store ONLY h (critical path) ----
        float oo[2][2][2];
#pragma unroll
        for (int h2 = 0; h2 < 2; h2++) {
            int b = b0 + wr * 16 + rl + h2 * 8;
            bool m = tt < (h2 ? sl1 : sl0);
#pragma unroll
            for (int jg = 0; jg < 2; jg++) {
                int j = jbase + jg * 8;
                float ho[2];
#pragma unroll
                for (int cc = 0; cc < 2; cc++) {
                    int q = h2 * 2 + cc;
                    const float* xR = (const float*)&xpre[h2][jg][0];
                    const float* xZ = (const float*)&xpre[h2][jg][1];
                    const float* xN = (const float*)&xpre[h2][jg][2];
                    const float* bR = (const float*)&biasv[0][jg];
                    const float* bZ = (const float*)&biasv[1][jg];
                    const float* bNp = (const float*)&biasv[2][jg];
                    float r = sigf(xR[cc] + d[jg * 3 + 0][q] + bR[cc]);
                    float z = sigf(xZ[cc] + d[jg * 3 + 1][q] + bZ[cc]);
                    float n = tanhfast(xN[cc] + r * (d[jg * 3 + 2][q] + bNp[cc]));
                    float hprev = hold[h2][jg][cc];
                    float hv = (1.0f - z) * n + z * hprev;
                    float hout = m ? hv : hprev;
                    hold[h2][jg][cc] = hout;
                    ho[cc] = hout;
                    oo[h2][jg][cc] = m ? hv : 0.0f;
                }
                __nv_bfloat16 hi0, lo0, hi1, lo1;
                split_bf16(ho[0], hi0, lo0);
                split_bf16(ho[1], hi1, lo1);
                __nv_bfloat162 hp; hp.x = hi0; hp.y = hi1;
                __nv_bfloat162 lq; lq.x = lo0; lq.y = lo1;
                *(__nv_bfloat162*)&hbd[(size_t)b * HN + j] = hp;
                *(__nv_bfloat162*)&hld[(size_t)b * HN + j] = lq;
            }
        }

        // ---- arrive: release-atomic after CTA-wide h-store visibility ----
        __syncthreads();
        if (i + 1 < Lg && tid == 0) bar_arrive(&g_bar[grp]);

        // ---- epilogue phase 2 (off critical path): g_out + direct logits atomics ----
        float lp[2] = {0.0f, 0.0f};
#pragma unroll
        for (int h2 = 0; h2 < 2; h2++) {
            int b = b0 + wr * 16 + rl + h2 * 8;
#pragma unroll
            for (int jg = 0; jg < 2; jg++) {
                int j = jbase + jg * 8;
                *(float2*)&g_out[(((size_t)dir * TN + tt) * BN + b) * HN + j] =
                    make_float2(oo[h2][jg][0], oo[h2][jg][1]);
                lp[h2] += oo[h2][jg][0] * ((const float*)&vv[jg])[0]
                        + oo[h2][jg][1] * ((const float*)&vv[jg])[1];
            }
        }
#pragma unroll
        for (int h2 = 0; h2 < 2; h2++) {
            lp[h2] += __shfl_xor_sync(0xffffffff, lp[h2], 1);
            lp[h2] += __shfl_xor_sync(0xffffffff, lp[h2], 2);
            if (ql == 0 && lp[h2] != 0.0f)
                atomicAdd(&g_logits[(size_t)(h2 ? sob1 : sob0) * TN + tt], lp[h2]);
        }
    }
}

// ---------------- fused softmax + weighted sum ----------------
__global__ __launch_bounds__(256) void attn_kernel(const int* __restrict__ seqlen,
                                                   float* __restrict__ out) {
    __shared__ float sa[256];
    __shared__ float red[256];
    int ob = blockIdx.x;
    int tid = threadIdx.x;
    int len = seqlen[ob];
    bool valid = (tid < TN) && (tid < len);
    float l = valid ? g_logits[(size_t)ob * TN + tid] : -1e30f;

    red[tid] = l;
    __syncthreads();
    for (int s = 128; s > 0; s >>= 1) {
        if (tid < s) red[tid] = fmaxf(red[tid], red[tid + s]);
        __syncthreads();
    }
    float mx = red[0];
    __syncthreads();
    float e = valid ? expf(l - mx) : 0.0f;
    red[tid] = e;
    __syncthreads();
    for (int s = 128; s > 0; s >>= 1) {
        if (tid < s) red[tid] += red[tid + s];
        __syncthreads();
    }
    sa[tid] = e / red[0];
    __syncthreads();

    int jb = g_inv[ob];
#pragma unroll
    for (int q = 0; q < 4; q++) {
        int h = q * 256 + tid;
        int d = (h >= HN);
        int hc = d ? h - HN : h;
        const float* base = g_out + ((size_t)d * TN * BN + jb) * HN + hc;
        float acc = 0.0f;
        for (int t = 0; t < len; t++)
            acc += sa[t] * base[(size_t)t * BN * HN];
        out[(size_t)ob * (2 * HN) + h] = acc;
    }
}

// ---------------- launch ----------------
extern "C" void kernel_launch(void* const* d_in, const int* in_sizes, int n_in,
                              void* d_out, int out_size) {
    const float* inp    = (const float*)d_in[0];
    const float* Wih_f  = (const float*)d_in[1];
    const float* Whh_f  = (const float*)d_in[2];
    const float* bih_f  = (const float*)d_in[3];
    const float* bhh_f  = (const float*)d_in[4];
    const float* Wih_b  = (const float*)d_in[5];
    const float* Whh_b  = (const float*)d_in[6];
    const float* bih_b  = (const float*)d_in[7];
    const float* bhh_b  = (const float*)d_in[8];
    const float* Wattn  = (const float*)d_in[9];
    const float* Wcomb  = (const float*)d_in[11];
    const int*   slen_s = (const int*)d_in[12];
    const int*   sidx   = (const int*)d_in[13];
    const int*   seqlen = (const int*)d_in[14];
    float* out = (float*)d_out;

    cudaFuncSetAttribute(persist_kernel,
                         cudaFuncAttributeMaxDynamicSharedMemorySize, SMEM_TOTAL);
    cudaFuncSetAttribute(proj_mma,
                         cudaFuncAttributeMaxDynamicSharedMemorySize, PSMEM);

    init_kernel<<<(2 * 2 * BN * HN + 255) / 256, 256>>>();
    prep_kernel<<<1, 1024>>>(Wattn, Wcomb, sidx);
    convi_kernel<<<(int)(((size_t)MN * KP + 255) / 256), 256>>>(inp);
    convw_kernel<<<(2 * GN * KP + 255) / 256, 256>>>(Wih_f, Wih_b);
    proj_mma<<<dim3(MN / 128, GN / 96, 2), 256, PSMEM>>>(bih_f, bih_b);
    persist_kernel<<<dim3(16, 4, 2), 256, SMEM_TOTAL>>>(Whh_f, Whh_b, bhh_f, bhh_b,
                                                        slen_s, sidx);
    attn_kernel<<<BN, 256>>>(seqlen, out);
}